// round 12
// baseline (speedup 1.0000x reference)
#include <cuda_runtime.h>
#include <cuda_bf16.h>
#include <math.h>
#include <stdint.h>

// ---------------- problem constants ----------------
#define NT     4096
#define DIM    1024
#define NHEAD  1002
#define SHORTN 1000
#define N0     9000
#define K0     256
#define N1     40257
#define K1     64
#define C0_END 10000

#define LOG2E  1.4426950408889634f
#define LN2    0.6931471805599453f

// ---------------- GEMM tiling ----------------
#define BM 128
#define BN 128
#define BK 32
#define SPAD 40          // smem row stride (bf16): conflict-free LDSM phases
#define SPAD4 72         // cluster-1 A tile row stride
#define NTILE1 5         // n-tiles per block in cluster-1 kernel
#define NB_H 8
#define NB_0 71
#define NB_1 63          // 315 n-tiles / 5 per block

// ---------------- static device scratch ----------------
// NOTE: Wh, W0b, W1b are stored PRE-SCALED by LOG2E (log2-domain logits out of
// the LSE GEMMs -> epilogue is a bare exp2). Assemble multiplies its dots by LN2.
__device__ __align__(16) __nv_bfloat16 g_xb  [NT * DIM];
__device__ __align__(16) __nv_bfloat16 g_Whb [NHEAD * DIM];
__device__ __align__(16) __nv_bfloat16 g_W0ab[K0 * DIM];
__device__ __align__(16) __nv_bfloat16 g_W0bb[N0 * K0];
__device__ __align__(16) __nv_bfloat16 g_W1ab[K1 * DIM];
__device__ __align__(16) __nv_bfloat16 g_W1bb[N1 * K1];
__device__ __align__(16) __nv_bfloat16 g_H0b [NT * K0];
__device__ __align__(16) __nv_bfloat16 g_H1b [NT * K1];

__device__ float g_psH[NT * NB_H];
__device__ float g_ps0[NT * NB_0];
__device__ float g_ps1[NT * NB_1];
__device__ float g_lseH[NT], g_lse0[NT], g_lse1[NT];
__device__ int   g_idx0[NT], g_idx1[NT], g_rank[NT], g_cnt[2];

__device__ __forceinline__ void mma_bf16(float c[4], uint32_t a0, uint32_t a1,
                                         uint32_t a2, uint32_t a3,
                                         uint32_t b0, uint32_t b1) {
    asm volatile(
        "mma.sync.aligned.m16n8k16.row.col.f32.bf16.bf16.f32 "
        "{%0,%1,%2,%3}, {%4,%5,%6,%7}, {%8,%9}, {%0,%1,%2,%3};"
        : "+f"(c[0]), "+f"(c[1]), "+f"(c[2]), "+f"(c[3])
        : "r"(a0), "r"(a1), "r"(a2), "r"(a3), "r"(b0), "r"(b1));
}

__device__ __forceinline__ uint32_t saddr(const void* p) {
    return (uint32_t)__cvta_generic_to_shared(p);
}
__device__ __forceinline__ void ldsm4(uint32_t& r0, uint32_t& r1, uint32_t& r2,
                                      uint32_t& r3, uint32_t a) {
    asm volatile("ldmatrix.sync.aligned.m8n8.x4.shared.b16 {%0,%1,%2,%3}, [%4];"
                 : "=r"(r0), "=r"(r1), "=r"(r2), "=r"(r3) : "r"(a));
}

__device__ __forceinline__ void cp16(void* smem, const void* gmem, bool valid) {
    uint32_t s = saddr(smem);
    int n = valid ? 16 : 0;
    asm volatile("cp.async.ca.shared.global [%0], [%1], 16, %2;\n"
                 :: "r"(s), "l"(gmem), "r"(n));
}
__device__ __forceinline__ void cp_commit() {
    asm volatile("cp.async.commit_group;\n");
}
template <int N>
__device__ __forceinline__ void cp_wait() {
    asm volatile("cp.async.wait_group %0;\n" :: "n"(N));
}

// ---------------- combined fp32 -> bf16 conversion (LSE weights pre-scaled) -----
__global__ void cvt_all(const float* __restrict__ x,  const float* __restrict__ Wh,
                        const float* __restrict__ W0a, const float* __restrict__ W0b,
                        const float* __restrict__ W1a, const float* __restrict__ W1b)
{
    const int nx  = NT * DIM / 4;
    const int nwh = NHEAD * DIM / 4;
    const int n0a = K0 * DIM / 4;
    const int n0b = N0 * K0 / 4;
    const int n1a = K1 * DIM / 4;
    const int n1b = N1 * K1 / 4;

    int i = blockIdx.x * blockDim.x + threadIdx.x;
    const float* s; __nv_bfloat16* d; float sc;
    if      (i < nx)                 { s = x;   d = g_xb;   sc = 1.f;   }
    else if ((i -= nx)  < nwh)       { s = Wh;  d = g_Whb;  sc = LOG2E; }
    else if ((i -= nwh) < n0a)       { s = W0a; d = g_W0ab; sc = 1.f;   }
    else if ((i -= n0a) < n0b)       { s = W0b; d = g_W0bb; sc = LOG2E; }
    else if ((i -= n0b) < n1a)       { s = W1a; d = g_W1ab; sc = 1.f;   }
    else if ((i -= n1a) < n1b)       { s = W1b; d = g_W1bb; sc = LOG2E; }
    else return;

    float4 v = ((const float4*)s)[i];
    __nv_bfloat162* d2 = (__nv_bfloat162*)d;
    d2[2 * i]     = __floats2bfloat162_rn(v.x * sc, v.y * sc);
    d2[2 * i + 1] = __floats2bfloat162_rn(v.z * sc, v.w * sc);
}

// ---------------- token partition by target cluster ----------------
__global__ void partition_kernel(const int* __restrict__ target) {
    __shared__ int c[2];
    if (threadIdx.x < 2) c[threadIdx.x] = 0;
    __syncthreads();
    for (int i = threadIdx.x; i < NT; i += blockDim.x) {
        int t = target[i];
        if (t >= SHORTN) {
            if (t < C0_END) { int s = atomicAdd(&c[0], 1); g_idx0[s] = i; g_rank[i] = s; }
            else            { int s = atomicAdd(&c[1], 1); g_idx1[s] = i; g_rank[i] = s; }
        } else {
            g_rank[i] = -1;
        }
    }
    __syncthreads();
    if (threadIdx.x < 2) g_cnt[threadIdx.x] = c[threadIdx.x];
}

// ---------------- shared-memory layouts (static, <48KB) ----------------
struct SmemT {
    __nv_bfloat16 As[2][BM][SPAD];
    __nv_bfloat16 Bs[2][BN][SPAD];
    float sm_s[2][BM];
};
struct Smem4T {
    __nv_bfloat16 As[BM][SPAD4];
    __nv_bfloat16 Bs[2][BN][SPAD];
    float sm_s[2][BM];
};
union SmemU { SmemT g; Smem4T c1; };

// ---------------- generic bf16 TC GEMM body ----------
// MODE 0: store bf16 C into H scratch.  MODE 1: fused exp2-sum partial
// (weights pre-scaled by LOG2E -> acc is already log2-domain).
// SEL: 0 = x->H0 proj, 1 = x->H1 proj, 2 = head LSE, 3 = cluster-0 LSE
template <int MODE, int SEL>
__device__ __forceinline__ void gemm_body(SmemT& sm, int bxe, int by)
{
    constexpr int N   = (SEL == 0) ? K0 : (SEL == 1) ? K1 :
                        (SEL == 2) ? NHEAD : N0;
    constexpr int K   = (SEL <= 2) ? DIM : K0;
    constexpr int nb  = (SEL == 2) ? NB_H : NB_0;
    constexpr int ldc = (SEL == 0) ? K0 : K1;
    constexpr int NIT = K / BK;

    const __nv_bfloat16* A = (SEL <= 2) ? g_xb : g_H0b;
    const __nv_bfloat16* B =
        (SEL == 0) ? g_W0ab : (SEL == 1) ? g_W1ab :
        (SEL == 2) ? g_Whb  : g_W0bb;
    const int* idx = (SEL == 0) ? g_idx0 : (SEL == 1) ? g_idx1 : nullptr;

    int Mv = NT;
    if constexpr (SEL == 0 || SEL == 3) Mv = g_cnt[0];
    if constexpr (SEL == 1) Mv = g_cnt[1];

    __nv_bfloat16* outC = (SEL == 0) ? g_H0b : g_H1b;
    float* ps = (SEL == 2) ? g_psH : g_ps0;

    int m0 = by * BM;
    if (m0 >= Mv) return;
    int n0 = bxe * BN;

    int tid  = threadIdx.x;
    int lane = tid & 31;
    int wid  = tid >> 5;
    int wm   = wid >> 1;
    int wn   = wid & 1;
    int g    = lane >> 2;
    int tg   = lane & 3;

    int lrow  = tid & 127;
    int lhalf = (tid >> 7) * 16;

    bool aval = (m0 + lrow) < Mv;
    int  arow = aval ? (idx ? idx[m0 + lrow] : (m0 + lrow)) : 0;
    bool bvalr = (n0 + lrow) < N;
    const __nv_bfloat16* Ag = A + (size_t)arow * K;
    const __nv_bfloat16* Bg = B + (size_t)(bvalr ? (n0 + lrow) : 0) * K;

    int a_lrow = wm * 32 + (lane & 15);
    int a_lcol = (lane >> 4) * 8;
    int b_lrow = wn * 64 + (lane & 7) + ((lane >> 4) & 1) * 8;
    int b_lcol = lane & 8;

    float acc[2][8][4];
#pragma unroll
    for (int im = 0; im < 2; im++)
#pragma unroll
        for (int jn = 0; jn < 8; jn++)
#pragma unroll
            for (int c = 0; c < 4; c++) acc[im][jn][c] = 0.f;

    auto load_stage = [&](int k0, int st) {
        cp16(&sm.As[st][lrow][lhalf + 0], Ag + k0 + lhalf + 0, aval);
        cp16(&sm.As[st][lrow][lhalf + 8], Ag + k0 + lhalf + 8, aval);
        cp16(&sm.Bs[st][lrow][lhalf + 0], Bg + k0 + lhalf + 0, bvalr);
        cp16(&sm.Bs[st][lrow][lhalf + 8], Bg + k0 + lhalf + 8, bvalr);
        cp_commit();
    };

    load_stage(0, 0);

#pragma unroll 1
    for (int it = 0; it < NIT; it++) {
        int st = it & 1;
        if (it + 1 < NIT) {
            load_stage((it + 1) * BK, st ^ 1);
            cp_wait<1>();
        } else {
            cp_wait<0>();
        }
        __syncthreads();

#pragma unroll
        for (int ks = 0; ks < BK; ks += 16) {
            uint32_t a[2][4];
            ldsm4(a[0][0], a[0][1], a[0][2], a[0][3],
                  saddr(&sm.As[st][a_lrow][ks + a_lcol]));
            ldsm4(a[1][0], a[1][1], a[1][2], a[1][3],
                  saddr(&sm.As[st][a_lrow + 16][ks + a_lcol]));
#pragma unroll
            for (int p = 0; p < 4; p++) {
                uint32_t b0, b1, b2, b3;
                ldsm4(b0, b1, b2, b3,
                      saddr(&sm.Bs[st][b_lrow + p * 16][ks + b_lcol]));
                mma_bf16(acc[0][2 * p],     a[0][0], a[0][1], a[0][2], a[0][3], b0, b1);
                mma_bf16(acc[1][2 * p],     a[1][0], a[1][1], a[1][2], a[1][3], b0, b1);
                mma_bf16(acc[0][2 * p + 1], a[0][0], a[0][1], a[0][2], a[0][3], b2, b3);
                mma_bf16(acc[1][2 * p + 1], a[1][0], a[1][1], a[1][2], a[1][3], b2, b3);
            }
        }
        __syncthreads();
    }

    if constexpr (MODE == 0) {
#pragma unroll
        for (int im = 0; im < 2; im++)
#pragma unroll
            for (int h = 0; h < 2; h++) {
                int gr = m0 + wm * 32 + im * 16 + h * 8 + g;
                if (gr < Mv) {
#pragma unroll
                    for (int jn = 0; jn < 8; jn++) {
                        int gc = n0 + wn * 64 + jn * 8 + 2 * tg;
                        if (gc < N) {
                            *(__nv_bfloat162*)&outC[(size_t)gr * ldc + gc] =
                                __floats2bfloat162_rn(acc[im][jn][h * 2],
                                                      acc[im][jn][h * 2 + 1]);
                        }
                    }
                }
            }
    } else {
        bool full = (n0 + BN <= N);
#pragma unroll
        for (int im = 0; im < 2; im++)
#pragma unroll
            for (int h = 0; h < 2; h++) {
                int rowl = wm * 32 + im * 16 + h * 8 + g;
                float s = 0.f;
                if (full) {
#pragma unroll
                    for (int jn = 0; jn < 8; jn++)
#pragma unroll
                        for (int c = 0; c < 2; c++)
                            s += exp2f(acc[im][jn][h * 2 + c]);
                } else {
#pragma unroll
                    for (int jn = 0; jn < 8; jn++)
#pragma unroll
                        for (int c = 0; c < 2; c++) {
                            int gc = n0 + wn * 64 + jn * 8 + 2 * tg + c;
                            if (gc < N)
                                s += exp2f(acc[im][jn][h * 2 + c]);
                        }
                }
                s += __shfl_xor_sync(0xffffffffu, s, 1);
                s += __shfl_xor_sync(0xffffffffu, s, 2);
                if (tg == 0) sm.sm_s[wn][rowl] = s;
            }
        __syncthreads();
        if (tid < BM) {
            float s = sm.sm_s[0][tid] + sm.sm_s[1][tid];
            int gr = m0 + tid;
            if (gr < Mv) ps[(size_t)gr * nb + bxe] = s;
        }
    }
}

// ---------------- cluster-1 LSE GEMM body: A resident, 2-stage B chunks ----------
__device__ __forceinline__ void gemm4_body(Smem4T& sm, int bx, int by)
{
    int Mv = g_cnt[1];
    int m0 = by * BM;
    if (m0 >= Mv) return;

    int tid  = threadIdx.x;
    int lane = tid & 31;
    int wid  = tid >> 5;
    int wm   = wid >> 1;
    int wn   = wid & 1;
    int g    = lane >> 2;
    int tg   = lane & 3;

    int lrow  = tid & 127;
    int half  = tid >> 7;

    bool aval = (m0 + lrow) < Mv;
    const __nv_bfloat16* Ag = g_H1b + (size_t)(aval ? (m0 + lrow) : 0) * K1;
    {
        int c0 = half * 32;
#pragma unroll
        for (int q = 0; q < 4; q++)
            cp16(&sm.As[lrow][c0 + q * 8], Ag + c0 + q * 8, aval);
    }

    auto load_B = [&](int s) {
        int t = s >> 1, c = s & 1;
        int n0 = (bx * NTILE1 + t) * BN;
        int brow = n0 + lrow;
        bool bval = brow < N1;
        const __nv_bfloat16* Bg = g_W1bb + (size_t)(bval ? brow : 0) * K1 + c * BK;
        int c0 = half * 16;
        cp16(&sm.Bs[s & 1][lrow][c0 + 0], Bg + c0 + 0, bval);
        cp16(&sm.Bs[s & 1][lrow][c0 + 8], Bg + c0 + 8, bval);
        cp_commit();
    };

    load_B(0);

    int a_lrow = wm * 32 + (lane & 15);
    int a_lcol = (lane >> 4) * 8;
    int b_lrow = wn * 64 + (lane & 7) + ((lane >> 4) & 1) * 8;
    int b_lcol = lane & 8;

    float acc[2][8][4];
    float srun[2][2];
#pragma unroll
    for (int im = 0; im < 2; im++)
#pragma unroll
        for (int h = 0; h < 2; h++) srun[im][h] = 0.f;

    constexpr int NCHUNK = NTILE1 * 2;
#pragma unroll 1
    for (int s = 0; s < NCHUNK; s++) {
        int t = s >> 1, c = s & 1, st = s & 1;
        if (s + 1 < NCHUNK) { load_B(s + 1); cp_wait<1>(); }
        else                { cp_wait<0>(); }
        __syncthreads();

        if (c == 0) {
#pragma unroll
            for (int im = 0; im < 2; im++)
#pragma unroll
                for (int jn = 0; jn < 8; jn++)
#pragma unroll
                    for (int q = 0; q < 4; q++) acc[im][jn][q] = 0.f;
        }

#pragma unroll
        for (int ks = 0; ks < BK; ks += 16) {
            uint32_t a[2][4];
            ldsm4(a[0][0], a[0][1], a[0][2], a[0][3],
                  saddr(&sm.As[a_lrow][c * BK + ks + a_lcol]));
            ldsm4(a[1][0], a[1][1], a[1][2], a[1][3],
                  saddr(&sm.As[a_lrow + 16][c * BK + ks + a_lcol]));
#pragma unroll
            for (int p = 0; p < 4; p++) {
                uint32_t b0, b1, b2, b3;
                ldsm4(b0, b1, b2, b3,
                      saddr(&sm.Bs[st][b_lrow + p * 16][ks + b_lcol]));
                mma_bf16(acc[0][2 * p],     a[0][0], a[0][1], a[0][2], a[0][3], b0, b1);
                mma_bf16(acc[1][2 * p],     a[1][0], a[1][1], a[1][2], a[1][3], b0, b1);
                mma_bf16(acc[0][2 * p + 1], a[0][0], a[0][1], a[0][2], a[0][3], b2, b3);
                mma_bf16(acc[1][2 * p + 1], a[1][0], a[1][1], a[1][2], a[1][3], b2, b3);
            }
        }

        if (c == 1) {
            int n0 = (bx * NTILE1 + t) * BN;
            bool full = (n0 + BN <= N1);
#pragma unroll
            for (int im = 0; im < 2; im++)
#pragma unroll
                for (int h = 0; h < 2; h++) {
                    float sv = 0.f;
                    if (full) {
#pragma unroll
                        for (int jn = 0; jn < 8; jn++)
#pragma unroll
                            for (int cc = 0; cc < 2; cc++)
                                sv += exp2f(acc[im][jn][h * 2 + cc]);
                    } else {
#pragma unroll
                        for (int jn = 0; jn < 8; jn++)
#pragma unroll
                            for (int cc = 0; cc < 2; cc++) {
                                int gc = n0 + wn * 64 + jn * 8 + 2 * tg + cc;
                                if (gc < N1)
                                    sv += exp2f(acc[im][jn][h * 2 + cc]);
                            }
                    }
                    srun[im][h] += sv;
                }
        }
        __syncthreads();
    }

#pragma unroll
    for (int im = 0; im < 2; im++)
#pragma unroll
        for (int h = 0; h < 2; h++) {
            int rowl = wm * 32 + im * 16 + h * 8 + g;
            float s = srun[im][h];
            s += __shfl_xor_sync(0xffffffffu, s, 1);
            s += __shfl_xor_sync(0xffffffffu, s, 2);
            if (tg == 0) sm.sm_s[wn][rowl] = s;
        }
    __syncthreads();
    if (tid < BM) {
        float s = sm.sm_s[0][tid] + sm.sm_s[1][tid];
        int gr = m0 + tid;
        if (gr < Mv) g_ps1[(size_t)gr * NB_1 + bx] = s;
    }
}

// ---------------- stage A: projections only (head-LSE moved to stage B) --------
// grid.x: [0,2) -> proj0, [2,3) -> proj1
__global__ __launch_bounds__(256, 2) void stageA_kernel()
{
    __shared__ SmemT sm;
    int bx = blockIdx.x, by = blockIdx.y;
    if (bx < 2) gemm_body<0, 0>(sm, bx, by);
    else        gemm_body<0, 1>(sm, bx - 2, by);
}

// ---------------- stage B: cluster-1 + head + cluster-0, co-scheduled ----------
// grid.x: [0,63) -> cluster-1, [63,71) -> head LSE, [71,142) -> cluster-0
__global__ __launch_bounds__(256, 2) void stageB_kernel()
{
    __shared__ SmemU sm;
    int bx = blockIdx.x;
    if (bx < NB_1)           gemm4_body(sm.c1, bx, blockIdx.y);
    else if (bx < NB_1 + 8)  gemm_body<1, 2>(sm.g, bx - NB_1, blockIdx.y);
    else                     gemm_body<1, 3>(sm.g, bx - NB_1 - 8, blockIdx.y);
}

// ---------------- merge partial exp-sums -> lse per token (one launch) ----------
__global__ void reduce_all_kernel()
{
    int gw   = (blockIdx.x * blockDim.x + threadIdx.x) >> 5;
    int lane = threadIdx.x & 31;
    int seg  = gw >> 12;        // NT = 4096 warps per segment
    int w    = gw & (NT - 1);

    int nb; const float* ps; float* lse_out; const int* idx; int Mv;
    if (seg == 0)      { nb = NB_H; ps = g_psH; lse_out = g_lseH; idx = nullptr; Mv = NT; }
    else if (seg == 1) { nb = NB_0; ps = g_ps0; lse_out = g_lse0; idx = g_idx0;  Mv = g_cnt[0]; }
    else               { nb = NB_1; ps = g_ps1; lse_out = g_lse1; idx = g_idx1;  Mv = g_cnt[1]; }
    if (w >= Mv) return;

    float s = 0.f;
    for (int b = lane; b < nb; b += 32)
        s += ps[(size_t)w * nb + b];
#pragma unroll
    for (int off = 16; off >= 1; off >>= 1)
        s += __shfl_xor_sync(0xffffffffu, s, off);
    if (lane == 0) {
        int tok = idx ? idx[w] : w;
        lse_out[tok] = logf(s);
    }
}

// ---------------- per-token target gather + output assembly ----------------
// B-side weights are pre-scaled by LOG2E -> dots need *LN2 to return to nats.
__global__ void assemble_kernel(const int* __restrict__ target, float* __restrict__ out)
{
    int w    = (blockIdx.x * blockDim.x + threadIdx.x) >> 5;
    int lane = threadIdx.x & 31;
    if (w >= NT) return;
    int i = w;
    int t = target[i];

    const __nv_bfloat16* va; const __nv_bfloat16* vb; int len;
    if (t < SHORTN)      { va = g_xb  + (size_t)i * DIM;           vb = g_Whb  + (size_t)t * DIM;             len = DIM; }
    else if (t < C0_END) { va = g_H0b + (size_t)g_rank[i] * K0;    vb = g_W0bb + (size_t)(t - SHORTN) * K0;   len = K0;  }
    else                 { va = g_H1b + (size_t)g_rank[i] * K1;    vb = g_W1bb + (size_t)(t - C0_END) * K1;   len = K1;  }

    float d = 0.f;
    for (int k = lane; k < len; k += 32)
        d += __bfloat162float(va[k]) * __bfloat162float(vb[k]);

    float dh = 0.f;
    if (t >= SHORTN) {
        const __nv_bfloat16* wh = g_Whb + (size_t)((t < C0_END) ? SHORTN : (SHORTN + 1)) * DIM;
        const __nv_bfloat16* xr = g_xb + (size_t)i * DIM;
        for (int k = lane; k < DIM; k += 32)
            dh += __bfloat162float(xr[k]) * __bfloat162float(wh[k]);
    }
#pragma unroll
    for (int off = 16; off >= 1; off >>= 1) {
        d  += __shfl_xor_sync(0xffffffffu, d,  off);
        dh += __shfl_xor_sync(0xffffffffu, dh, off);
    }
    if (lane == 0) {
        d  *= LN2;   // undo LOG2E weight pre-scale
        dh *= LN2;
        float o;
        if (t < SHORTN)      o = d - g_lseH[i];
        else if (t < C0_END) o = (d - g_lse0[i]) + (dh - g_lseH[i]);
        else                 o = (d - g_lse1[i]) + (dh - g_lseH[i]);
        out[i] = o;
    }
}

// ---------------- deterministic loss = -mean(output) ----------------
__global__ void loss_kernel(float* __restrict__ out, int loss_idx)
{
    __shared__ float sh[1024];
    float s = 0.f;
    for (int i = threadIdx.x; i < NT; i += 1024) s += out[i];
    sh[threadIdx.x] = s;
    __syncthreads();
    for (int o = 512; o > 0; o >>= 1) {
        if (threadIdx.x < o) sh[threadIdx.x] += sh[threadIdx.x + o];
        __syncthreads();
    }
    if (threadIdx.x == 0) out[loss_idx] = -sh[0] / (float)NT;
}

// ---------------- launcher (pure kernel launches, static smem only) ----------------
extern "C" void kernel_launch(void* const* d_in, const int* in_sizes, int n_in,
                              void* d_out, int out_size)
{
    const float* x      = (const float*)d_in[0];
    const int*   target = (const int*)  d_in[1];
    const float* Wh     = (const float*)d_in[2];
    const float* W0a    = (const float*)d_in[3];
    const float* W0b    = (const float*)d_in[4];
    const float* W1a    = (const float*)d_in[5];
    const float* W1b    = (const float*)d_in[6];
    float* out = (float*)d_out;

    partition_kernel<<<1, 1024>>>(target);
    {
        const int total4 = NT * DIM / 4 + NHEAD * DIM / 4 + K0 * DIM / 4 +
                           N0 * K0 / 4 + K1 * DIM / 4 + N1 * K1 / 4;
        cvt_all<<<(total4 + 255) / 256, 256>>>(x, Wh, W0a, W0b, W1a, W1b);
    }

    // stage A: projections only (fast)
    stageA_kernel<<<dim3(3, NT / BM), 256>>>();
    // stage B: cluster-1 + head + cluster-0, one big co-scheduled launch
    stageB_kernel<<<dim3(NB_1 + NB_H + NB_0, NT / BM), 256>>>();

    reduce_all_kernel<<<3 * NT * 32 / 256, 256>>>();
    assemble_kernel<<<NT * 32 / 256, 256>>>(target, out);
    loss_kernel<<<1, 1024>>>(out, out_size - 1);
}

// round 16
// speedup vs baseline: 1.2390x; 1.2390x over previous
#include <cuda_runtime.h>
#include <cuda_bf16.h>
#include <math.h>
#include <stdint.h>

// ---------------- problem constants ----------------
#define NT     4096
#define DIM    1024
#define NHEAD  1002
#define SHORTN 1000
#define N0     9000
#define K0     256
#define N1     40257
#define K1     64
#define C0_END 10000

#define LOG2E  1.4426950408889634f
#define LN2    0.6931471805599453f

// ---------------- GEMM tiling ----------------
#define BM 128
#define BN 128
#define BK 32
#define SPAD 40          // smem row stride (bf16): conflict-free LDSM phases
#define SPAD4 72         // cluster-1 A tile row stride
#define NTILE1 5         // n-tiles per block in cluster-1 kernel
#define NB_H 8
#define NB_0 71
#define NB_1 63          // 315 n-tiles / 5 per block

// ---------------- static device scratch ----------------
// NOTE: Wh, W0b, W1b stored PRE-SCALED by LOG2E (log2-domain logits out of the
// LSE GEMMs -> epilogue is a bare exp2). Assemble multiplies its dots by LN2.
__device__ __align__(16) __nv_bfloat16 g_xb  [NT * DIM];
__device__ __align__(16) __nv_bfloat16 g_Whb [NHEAD * DIM];
__device__ __align__(16) __nv_bfloat16 g_W0ab[K0 * DIM];
__device__ __align__(16) __nv_bfloat16 g_W0bb[N0 * K0];
__device__ __align__(16) __nv_bfloat16 g_W1ab[K1 * DIM];
__device__ __align__(16) __nv_bfloat16 g_W1bb[N1 * K1];
__device__ __align__(16) __nv_bfloat16 g_H0b [NT * K0];
__device__ __align__(16) __nv_bfloat16 g_H1b [NT * K1];

__device__ float g_psH[NT * NB_H];
__device__ float g_ps0[NT * NB_0];
__device__ float g_ps1[NT * NB_1];
__device__ float g_lseH[NT], g_lse0[NT], g_lse1[NT];
__device__ int   g_idx0[NT], g_idx1[NT], g_rank[NT], g_cnt[2];

__device__ __forceinline__ void mma_bf16(float c[4], uint32_t a0, uint32_t a1,
                                         uint32_t a2, uint32_t a3,
                                         uint32_t b0, uint32_t b1) {
    asm volatile(
        "mma.sync.aligned.m16n8k16.row.col.f32.bf16.bf16.f32 "
        "{%0,%1,%2,%3}, {%4,%5,%6,%7}, {%8,%9}, {%0,%1,%2,%3};"
        : "+f"(c[0]), "+f"(c[1]), "+f"(c[2]), "+f"(c[3])
        : "r"(a0), "r"(a1), "r"(a2), "r"(a3), "r"(b0), "r"(b1));
}

__device__ __forceinline__ uint32_t saddr(const void* p) {
    return (uint32_t)__cvta_generic_to_shared(p);
}
__device__ __forceinline__ void ldsm4(uint32_t& r0, uint32_t& r1, uint32_t& r2,
                                      uint32_t& r3, uint32_t a) {
    asm volatile("ldmatrix.sync.aligned.m8n8.x4.shared.b16 {%0,%1,%2,%3}, [%4];"
                 : "=r"(r0), "=r"(r1), "=r"(r2), "=r"(r3) : "r"(a));
}

__device__ __forceinline__ void cp16(void* smem, const void* gmem, bool valid) {
    uint32_t s = saddr(smem);
    int n = valid ? 16 : 0;
    asm volatile("cp.async.ca.shared.global [%0], [%1], 16, %2;\n"
                 :: "r"(s), "l"(gmem), "r"(n));
}
__device__ __forceinline__ void cp_commit() {
    asm volatile("cp.async.commit_group;\n");
}
template <int N>
__device__ __forceinline__ void cp_wait() {
    asm volatile("cp.async.wait_group %0;\n" :: "n"(N));
}

// ---------------- combined fp32 -> bf16 conversion (LSE weights pre-scaled) -----
__global__ void cvt_all(const float* __restrict__ x,  const float* __restrict__ Wh,
                        const float* __restrict__ W0a, const float* __restrict__ W0b,
                        const float* __restrict__ W1a, const float* __restrict__ W1b)
{
    const int nx  = NT * DIM / 4;
    const int nwh = NHEAD * DIM / 4;
    const int n0a = K0 * DIM / 4;
    const int n0b = N0 * K0 / 4;
    const int n1a = K1 * DIM / 4;
    const int n1b = N1 * K1 / 4;

    int i = blockIdx.x * blockDim.x + threadIdx.x;
    const float* s; __nv_bfloat16* d; float sc;
    if      (i < nx)                 { s = x;   d = g_xb;   sc = 1.f;   }
    else if ((i -= nx)  < nwh)       { s = Wh;  d = g_Whb;  sc = LOG2E; }
    else if ((i -= nwh) < n0a)       { s = W0a; d = g_W0ab; sc = 1.f;   }
    else if ((i -= n0a) < n0b)       { s = W0b; d = g_W0bb; sc = LOG2E; }
    else if ((i -= n0b) < n1a)       { s = W1a; d = g_W1ab; sc = 1.f;   }
    else if ((i -= n1a) < n1b)       { s = W1b; d = g_W1bb; sc = LOG2E; }
    else return;

    float4 v = ((const float4*)s)[i];
    __nv_bfloat162* d2 = (__nv_bfloat162*)d;
    d2[2 * i]     = __floats2bfloat162_rn(v.x * sc, v.y * sc);
    d2[2 * i + 1] = __floats2bfloat162_rn(v.z * sc, v.w * sc);
}

// ---------------- token partition by target cluster ----------------
__global__ void partition_kernel(const int* __restrict__ target) {
    __shared__ int c[2];
    if (threadIdx.x < 2) c[threadIdx.x] = 0;
    __syncthreads();
    for (int i = threadIdx.x; i < NT; i += blockDim.x) {
        int t = target[i];
        if (t >= SHORTN) {
            if (t < C0_END) { int s = atomicAdd(&c[0], 1); g_idx0[s] = i; g_rank[i] = s; }
            else            { int s = atomicAdd(&c[1], 1); g_idx1[s] = i; g_rank[i] = s; }
        } else {
            g_rank[i] = -1;
        }
    }
    __syncthreads();
    if (threadIdx.x < 2) g_cnt[threadIdx.x] = c[threadIdx.x];
}

// ---------------- shared-memory layouts (static, <48KB) ----------------
struct SmemT {
    __nv_bfloat16 As[2][BM][SPAD];
    __nv_bfloat16 Bs[2][BN][SPAD];
    float sm_s[2][BM];
};
struct Smem4T {
    __nv_bfloat16 As[BM][SPAD4];
    __nv_bfloat16 Bs[2][BN][SPAD];
    float sm_s[2][BM];
};
union SmemU { SmemT g; Smem4T c1; };

// ---------------- generic bf16 TC GEMM body ----------
// MODE 0: store bf16 C into H scratch.  MODE 1: fused exp2-sum partial
// (weights pre-scaled by LOG2E -> acc is already log2-domain).
// SEL: 0 = x->H0 proj, 1 = x->H1 proj, 2 = head LSE, 3 = cluster-0 LSE
template <int MODE, int SEL>
__device__ __forceinline__ void gemm_body(SmemT& sm, int bxe, int by)
{
    constexpr int N   = (SEL == 0) ? K0 : (SEL == 1) ? K1 :
                        (SEL == 2) ? NHEAD : N0;
    constexpr int K   = (SEL <= 2) ? DIM : K0;
    constexpr int nb  = (SEL == 2) ? NB_H : NB_0;
    constexpr int ldc = (SEL == 0) ? K0 : K1;
    constexpr int NIT = K / BK;

    const __nv_bfloat16* A = (SEL <= 2) ? g_xb : g_H0b;
    const __nv_bfloat16* B =
        (SEL == 0) ? g_W0ab : (SEL == 1) ? g_W1ab :
        (SEL == 2) ? g_Whb  : g_W0bb;
    const int* idx = (SEL == 0) ? g_idx0 : (SEL == 1) ? g_idx1 : nullptr;

    int Mv = NT;
    if constexpr (SEL == 0 || SEL == 3) Mv = g_cnt[0];
    if constexpr (SEL == 1) Mv = g_cnt[1];

    __nv_bfloat16* outC = (SEL == 0) ? g_H0b : g_H1b;
    float* ps = (SEL == 2) ? g_psH : g_ps0;

    int m0 = by * BM;
    if (m0 >= Mv) return;
    int n0 = bxe * BN;

    int tid  = threadIdx.x;
    int lane = tid & 31;
    int wid  = tid >> 5;
    int wm   = wid >> 1;
    int wn   = wid & 1;
    int g    = lane >> 2;
    int tg   = lane & 3;

    int lrow  = tid & 127;
    int lhalf = (tid >> 7) * 16;

    bool aval = (m0 + lrow) < Mv;
    int  arow = aval ? (idx ? idx[m0 + lrow] : (m0 + lrow)) : 0;
    bool bvalr = (n0 + lrow) < N;
    const __nv_bfloat16* Ag = A + (size_t)arow * K;
    const __nv_bfloat16* Bg = B + (size_t)(bvalr ? (n0 + lrow) : 0) * K;

    int a_lrow = wm * 32 + (lane & 15);
    int a_lcol = (lane >> 4) * 8;
    int b_lrow = wn * 64 + (lane & 7) + ((lane >> 4) & 1) * 8;
    int b_lcol = lane & 8;

    float acc[2][8][4];
#pragma unroll
    for (int im = 0; im < 2; im++)
#pragma unroll
        for (int jn = 0; jn < 8; jn++)
#pragma unroll
            for (int c = 0; c < 4; c++) acc[im][jn][c] = 0.f;

    auto load_stage = [&](int k0, int st) {
        cp16(&sm.As[st][lrow][lhalf + 0], Ag + k0 + lhalf + 0, aval);
        cp16(&sm.As[st][lrow][lhalf + 8], Ag + k0 + lhalf + 8, aval);
        cp16(&sm.Bs[st][lrow][lhalf + 0], Bg + k0 + lhalf + 0, bvalr);
        cp16(&sm.Bs[st][lrow][lhalf + 8], Bg + k0 + lhalf + 8, bvalr);
        cp_commit();
    };

    load_stage(0, 0);

#pragma unroll 1
    for (int it = 0; it < NIT; it++) {
        int st = it & 1;
        if (it + 1 < NIT) {
            load_stage((it + 1) * BK, st ^ 1);
            cp_wait<1>();
        } else {
            cp_wait<0>();
        }
        __syncthreads();

#pragma unroll
        for (int ks = 0; ks < BK; ks += 16) {
            uint32_t a[2][4];
            ldsm4(a[0][0], a[0][1], a[0][2], a[0][3],
                  saddr(&sm.As[st][a_lrow][ks + a_lcol]));
            ldsm4(a[1][0], a[1][1], a[1][2], a[1][3],
                  saddr(&sm.As[st][a_lrow + 16][ks + a_lcol]));
#pragma unroll
            for (int p = 0; p < 4; p++) {
                uint32_t b0, b1, b2, b3;
                ldsm4(b0, b1, b2, b3,
                      saddr(&sm.Bs[st][b_lrow + p * 16][ks + b_lcol]));
                mma_bf16(acc[0][2 * p],     a[0][0], a[0][1], a[0][2], a[0][3], b0, b1);
                mma_bf16(acc[1][2 * p],     a[1][0], a[1][1], a[1][2], a[1][3], b0, b1);
                mma_bf16(acc[0][2 * p + 1], a[0][0], a[0][1], a[0][2], a[0][3], b2, b3);
                mma_bf16(acc[1][2 * p + 1], a[1][0], a[1][1], a[1][2], a[1][3], b2, b3);
            }
        }
        __syncthreads();
    }

    if constexpr (MODE == 0) {
#pragma unroll
        for (int im = 0; im < 2; im++)
#pragma unroll
            for (int h = 0; h < 2; h++) {
                int gr = m0 + wm * 32 + im * 16 + h * 8 + g;
                if (gr < Mv) {
#pragma unroll
                    for (int jn = 0; jn < 8; jn++) {
                        int gc = n0 + wn * 64 + jn * 8 + 2 * tg;
                        if (gc < N) {
                            *(__nv_bfloat162*)&outC[(size_t)gr * ldc + gc] =
                                __floats2bfloat162_rn(acc[im][jn][h * 2],
                                                      acc[im][jn][h * 2 + 1]);
                        }
                    }
                }
            }
    } else {
        bool full = (n0 + BN <= N);
#pragma unroll
        for (int im = 0; im < 2; im++)
#pragma unroll
            for (int h = 0; h < 2; h++) {
                int rowl = wm * 32 + im * 16 + h * 8 + g;
                float s = 0.f;
                if (full) {
#pragma unroll
                    for (int jn = 0; jn < 8; jn++)
#pragma unroll
                        for (int c = 0; c < 2; c++)
                            s += exp2f(acc[im][jn][h * 2 + c]);
                } else {
#pragma unroll
                    for (int jn = 0; jn < 8; jn++)
#pragma unroll
                        for (int c = 0; c < 2; c++) {
                            int gc = n0 + wn * 64 + jn * 8 + 2 * tg + c;
                            if (gc < N)
                                s += exp2f(acc[im][jn][h * 2 + c]);
                        }
                }
                s += __shfl_xor_sync(0xffffffffu, s, 1);
                s += __shfl_xor_sync(0xffffffffu, s, 2);
                if (tg == 0) sm.sm_s[wn][rowl] = s;
            }
        __syncthreads();
        if (tid < BM) {
            float s = sm.sm_s[0][tid] + sm.sm_s[1][tid];
            int gr = m0 + tid;
            if (gr < Mv) ps[(size_t)gr * nb + bxe] = s;
        }
    }
}

// ---------------- cluster-1 LSE GEMM body: A resident, 2-stage B chunks ----------
__device__ __forceinline__ void gemm4_body(Smem4T& sm, int bx, int by)
{
    int Mv = g_cnt[1];
    int m0 = by * BM;
    if (m0 >= Mv) return;

    int tid  = threadIdx.x;
    int lane = tid & 31;
    int wid  = tid >> 5;
    int wm   = wid >> 1;
    int wn   = wid & 1;
    int g    = lane >> 2;
    int tg   = lane & 3;

    int lrow  = tid & 127;
    int half  = tid >> 7;

    bool aval = (m0 + lrow) < Mv;
    const __nv_bfloat16* Ag = g_H1b + (size_t)(aval ? (m0 + lrow) : 0) * K1;
    {
        int c0 = half * 32;
#pragma unroll
        for (int q = 0; q < 4; q++)
            cp16(&sm.As[lrow][c0 + q * 8], Ag + c0 + q * 8, aval);
    }

    auto load_B = [&](int s) {
        int t = s >> 1, c = s & 1;
        int n0 = (bx * NTILE1 + t) * BN;
        int brow = n0 + lrow;
        bool bval = brow < N1;
        const __nv_bfloat16* Bg = g_W1bb + (size_t)(bval ? brow : 0) * K1 + c * BK;
        int c0 = half * 16;
        cp16(&sm.Bs[s & 1][lrow][c0 + 0], Bg + c0 + 0, bval);
        cp16(&sm.Bs[s & 1][lrow][c0 + 8], Bg + c0 + 8, bval);
        cp_commit();
    };

    load_B(0);

    int a_lrow = wm * 32 + (lane & 15);
    int a_lcol = (lane >> 4) * 8;
    int b_lrow = wn * 64 + (lane & 7) + ((lane >> 4) & 1) * 8;
    int b_lcol = lane & 8;

    float acc[2][8][4];
    float srun[2][2];
#pragma unroll
    for (int im = 0; im < 2; im++)
#pragma unroll
        for (int h = 0; h < 2; h++) srun[im][h] = 0.f;

    constexpr int NCHUNK = NTILE1 * 2;
#pragma unroll 1
    for (int s = 0; s < NCHUNK; s++) {
        int t = s >> 1, c = s & 1, st = s & 1;
        if (s + 1 < NCHUNK) { load_B(s + 1); cp_wait<1>(); }
        else                { cp_wait<0>(); }
        __syncthreads();

        if (c == 0) {
#pragma unroll
            for (int im = 0; im < 2; im++)
#pragma unroll
                for (int jn = 0; jn < 8; jn++)
#pragma unroll
                    for (int q = 0; q < 4; q++) acc[im][jn][q] = 0.f;
        }

#pragma unroll
        for (int ks = 0; ks < BK; ks += 16) {
            uint32_t a[2][4];
            ldsm4(a[0][0], a[0][1], a[0][2], a[0][3],
                  saddr(&sm.As[a_lrow][c * BK + ks + a_lcol]));
            ldsm4(a[1][0], a[1][1], a[1][2], a[1][3],
                  saddr(&sm.As[a_lrow + 16][c * BK + ks + a_lcol]));
#pragma unroll
            for (int p = 0; p < 4; p++) {
                uint32_t b0, b1, b2, b3;
                ldsm4(b0, b1, b2, b3,
                      saddr(&sm.Bs[st][b_lrow + p * 16][ks + b_lcol]));
                mma_bf16(acc[0][2 * p],     a[0][0], a[0][1], a[0][2], a[0][3], b0, b1);
                mma_bf16(acc[1][2 * p],     a[1][0], a[1][1], a[1][2], a[1][3], b0, b1);
                mma_bf16(acc[0][2 * p + 1], a[0][0], a[0][1], a[0][2], a[0][3], b2, b3);
                mma_bf16(acc[1][2 * p + 1], a[1][0], a[1][1], a[1][2], a[1][3], b2, b3);
            }
        }

        if (c == 1) {
            int n0 = (bx * NTILE1 + t) * BN;
            bool full = (n0 + BN <= N1);
#pragma unroll
            for (int im = 0; im < 2; im++)
#pragma unroll
                for (int h = 0; h < 2; h++) {
                    float sv = 0.f;
                    if (full) {
#pragma unroll
                        for (int jn = 0; jn < 8; jn++)
#pragma unroll
                            for (int cc = 0; cc < 2; cc++)
                                sv += exp2f(acc[im][jn][h * 2 + cc]);
                    } else {
#pragma unroll
                        for (int jn = 0; jn < 8; jn++)
#pragma unroll
                            for (int cc = 0; cc < 2; cc++) {
                                int gc = n0 + wn * 64 + jn * 8 + 2 * tg + cc;
                                if (gc < N1)
                                    sv += exp2f(acc[im][jn][h * 2 + cc]);
                            }
                    }
                    srun[im][h] += sv;
                }
        }
        __syncthreads();
    }

#pragma unroll
    for (int im = 0; im < 2; im++)
#pragma unroll
        for (int h = 0; h < 2; h++) {
            int rowl = wm * 32 + im * 16 + h * 8 + g;
            float s = srun[im][h];
            s += __shfl_xor_sync(0xffffffffu, s, 1);
            s += __shfl_xor_sync(0xffffffffu, s, 2);
            if (tg == 0) sm.sm_s[wn][rowl] = s;
        }
    __syncthreads();
    if (tid < BM) {
        float s = sm.sm_s[0][tid] + sm.sm_s[1][tid];
        int gr = m0 + tid;
        if (gr < Mv) g_ps1[(size_t)gr * NB_1 + bx] = s;
    }
}

// ---------------- stage A: projections + head LSE (R10 topology) --------------
// grid.x: [0,2) -> proj0, [2,3) -> proj1, [3,11) -> head LSE
__global__ __launch_bounds__(256, 2) void stageA_kernel()
{
    __shared__ SmemT sm;
    int bx = blockIdx.x, by = blockIdx.y;
    if (bx < 2)      gemm_body<0, 0>(sm, bx, by);
    else if (bx < 3) gemm_body<0, 1>(sm, bx - 2, by);
    else             gemm_body<1, 2>(sm, bx - 3, by);
}

// ---------------- stage B: cluster-1 (long pole, first) + cluster-0 ------------
__global__ __launch_bounds__(256, 2) void stageB_kernel()
{
    __shared__ SmemU sm;
    int bx = blockIdx.x;
    if (bx < NB_1) gemm4_body(sm.c1, bx, blockIdx.y);
    else           gemm_body<1, 3>(sm.g, bx - NB_1, blockIdx.y);
}

// ---------------- merge partial exp-sums -> lse per token (one launch) ----------
__global__ void reduce_all_kernel()
{
    int gw   = (blockIdx.x * blockDim.x + threadIdx.x) >> 5;
    int lane = threadIdx.x & 31;
    int seg  = gw >> 12;        // NT = 4096 warps per segment
    int w    = gw & (NT - 1);

    int nb; const float* ps; float* lse_out; const int* idx; int Mv;
    if (seg == 0)      { nb = NB_H; ps = g_psH; lse_out = g_lseH; idx = nullptr; Mv = NT; }
    else if (seg == 1) { nb = NB_0; ps = g_ps0; lse_out = g_lse0; idx = g_idx0;  Mv = g_cnt[0]; }
    else               { nb = NB_1; ps = g_ps1; lse_out = g_lse1; idx = g_idx1;  Mv = g_cnt[1]; }
    if (w >= Mv) return;

    float s = 0.f;
    for (int b = lane; b < nb; b += 32)
        s += ps[(size_t)w * nb + b];
#pragma unroll
    for (int off = 16; off >= 1; off >>= 1)
        s += __shfl_xor_sync(0xffffffffu, s, off);
    if (lane == 0) {
        int tok = idx ? idx[w] : w;
        lse_out[tok] = logf(s);
    }
}

// ---------------- per-token target gather + output assembly ----------------
// B-side weights are pre-scaled by LOG2E -> dots need *LN2 to return to nats.
__global__ void assemble_kernel(const int* __restrict__ target, float* __restrict__ out)
{
    int w    = (blockIdx.x * blockDim.x + threadIdx.x) >> 5;
    int lane = threadIdx.x & 31;
    if (w >= NT) return;
    int i = w;
    int t = target[i];

    const __nv_bfloat16* va; const __nv_bfloat16* vb; int len;
    if (t < SHORTN)      { va = g_xb  + (size_t)i * DIM;           vb = g_Whb  + (size_t)t * DIM;             len = DIM; }
    else if (t < C0_END) { va = g_H0b + (size_t)g_rank[i] * K0;    vb = g_W0bb + (size_t)(t - SHORTN) * K0;   len = K0;  }
    else                 { va = g_H1b + (size_t)g_rank[i] * K1;    vb = g_W1bb + (size_t)(t - C0_END) * K1;   len = K1;  }

    float d = 0.f;
    for (int k = lane; k < len; k += 32)
        d += __bfloat162float(va[k]) * __bfloat162float(vb[k]);

    float dh = 0.f;
    if (t >= SHORTN) {
        const __nv_bfloat16* wh = g_Whb + (size_t)((t < C0_END) ? SHORTN : (SHORTN + 1)) * DIM;
        const __nv_bfloat16* xr = g_xb + (size_t)i * DIM;
        for (int k = lane; k < DIM; k += 32)
            dh += __bfloat162float(xr[k]) * __bfloat162float(wh[k]);
    }
#pragma unroll
    for (int off = 16; off >= 1; off >>= 1) {
        d  += __shfl_xor_sync(0xffffffffu, d,  off);
        dh += __shfl_xor_sync(0xffffffffu, dh, off);
    }
    if (lane == 0) {
        d  *= LN2;   // undo LOG2E weight pre-scale
        dh *= LN2;
        float o;
        if (t < SHORTN)      o = d - g_lseH[i];
        else if (t < C0_END) o = (d - g_lse0[i]) + (dh - g_lseH[i]);
        else                 o = (d - g_lse1[i]) + (dh - g_lseH[i]);
        out[i] = o;
    }
}

// ---------------- deterministic loss = -mean(output) ----------------
__global__ void loss_kernel(float* __restrict__ out, int loss_idx)
{
    __shared__ float sh[1024];
    float s = 0.f;
    for (int i = threadIdx.x; i < NT; i += 1024) s += out[i];
    sh[threadIdx.x] = s;
    __syncthreads();
    for (int o = 512; o > 0; o >>= 1) {
        if (threadIdx.x < o) sh[threadIdx.x] += sh[threadIdx.x + o];
        __syncthreads();
    }
    if (threadIdx.x == 0) out[loss_idx] = -sh[0] / (float)NT;
}

// ---------------- launcher (pure kernel launches, static smem only) ----------------
extern "C" void kernel_launch(void* const* d_in, const int* in_sizes, int n_in,
                              void* d_out, int out_size)
{
    const float* x      = (const float*)d_in[0];
    const int*   target = (const int*)  d_in[1];
    const float* Wh     = (const float*)d_in[2];
    const float* W0a    = (const float*)d_in[3];
    const float* W0b    = (const float*)d_in[4];
    const float* W1a    = (const float*)d_in[5];
    const float* W1b    = (const float*)d_in[6];
    float* out = (float*)d_out;

    partition_kernel<<<1, 1024>>>(target);
    {
        const int total4 = NT * DIM / 4 + NHEAD * DIM / 4 + K0 * DIM / 4 +
                           N0 * K0 / 4 + K1 * DIM / 4 + N1 * K1 / 4;
        cvt_all<<<(total4 + 255) / 256, 256>>>(x, Wh, W0a, W0b, W1a, W1b);
    }

    // stage A: projections + head LSE (R10 topology)
    stageA_kernel<<<dim3(11, NT / BM), 256>>>();
    // stage B: cluster-1 + cluster-0 LSE GEMMs
    stageB_kernel<<<dim3(NB_1 + NB_0, NT / BM), 256>>>();

    reduce_all_kernel<<<3 * NT * 32 / 256, 256>>>();
    assemble_kernel<<<NT * 32 / 256, 256>>>(target, out);
    loss_kernel<<<1, 1024>>>(out, out_size - 1);
}